// round 3
// baseline (speedup 1.0000x reference)
#include <cuda_runtime.h>

// CrossNet: xi_{l+1} = x0 * (xi_l . W[l]) + B[l] + xi_l, 3 layers.
// BATCH=16384, DIM=1024, ORDER=3 (read from in_sizes to stay shape-safe).
//
// Strategy: fully fused single pass. Warp-per-row; x0 and xi live in
// registers (8 x float4 each per lane). W,B staged to shared per block and
// reused across 8 rows. Only barrier is the one staging __syncthreads().
// HBM traffic = 64MB read + 64MB write -> ~20us floor.

#define CN_DIM 1024
#define CN_ORDER 3
#define CN_ROWS_PER_BLOCK 8
#define CN_THREADS 256
#define CN_VEC (CN_DIM / 4)        // 256 float4 per row
#define CN_V_PER_LANE 8            // 256 float4 / 32 lanes

__global__ __launch_bounds__(CN_THREADS, 2)
void crossnet_fused_kernel(const float* __restrict__ x0,
                           const float* __restrict__ W,
                           const float* __restrict__ B,
                           float* __restrict__ out,
                           int batch)
{
    __shared__ float sW[CN_ORDER * CN_DIM];
    __shared__ float sB[CN_ORDER * CN_DIM];

    const int tid = threadIdx.x;

    // Stage W and B into shared (24 KB), vectorized.
    {
        const float4* gW = (const float4*)W;
        const float4* gB = (const float4*)B;
        float4* shW = (float4*)sW;
        float4* shB = (float4*)sB;
        #pragma unroll
        for (int i = tid; i < CN_ORDER * CN_VEC; i += CN_THREADS) {
            shW[i] = gW[i];
            shB[i] = gB[i];
        }
    }
    __syncthreads();

    const int warp = tid >> 5;
    const int lane = tid & 31;
    const int row  = blockIdx.x * CN_ROWS_PER_BLOCK + warp;
    if (row >= batch) return;

    const float4* __restrict__ xrow = (const float4*)(x0 + (size_t)row * CN_DIM);

    // Load x0 row into registers; xi starts as a copy.
    float4 x[CN_V_PER_LANE];
    float4 xi[CN_V_PER_LANE];
    #pragma unroll
    for (int i = 0; i < CN_V_PER_LANE; i++) {
        x[i]  = xrow[i * 32 + lane];
        xi[i] = x[i];
    }

    #pragma unroll
    for (int l = 0; l < CN_ORDER; l++) {
        const float4* wl = (const float4*)(sW + l * CN_DIM);
        const float4* bl = (const float4*)(sB + l * CN_DIM);

        // Partial dot product for this lane's 32 elements.
        float p = 0.0f;
        #pragma unroll
        for (int i = 0; i < CN_V_PER_LANE; i++) {
            float4 w = wl[i * 32 + lane];
            p = fmaf(xi[i].x, w.x, p);
            p = fmaf(xi[i].y, w.y, p);
            p = fmaf(xi[i].z, w.z, p);
            p = fmaf(xi[i].w, w.w, p);
        }
        // Warp reduction -> s broadcast to all lanes.
        #pragma unroll
        for (int off = 16; off > 0; off >>= 1)
            p += __shfl_xor_sync(0xffffffffu, p, off);

        // xi = x0 * s + B[l] + xi
        #pragma unroll
        for (int i = 0; i < CN_V_PER_LANE; i++) {
            float4 b = bl[i * 32 + lane];
            xi[i].x = fmaf(x[i].x, p, xi[i].x + b.x);
            xi[i].y = fmaf(x[i].y, p, xi[i].y + b.y);
            xi[i].z = fmaf(x[i].z, p, xi[i].z + b.z);
            xi[i].w = fmaf(x[i].w, p, xi[i].w + b.w);
        }
    }

    // Write result.
    float4* __restrict__ orow = (float4*)(out + (size_t)row * CN_DIM);
    #pragma unroll
    for (int i = 0; i < CN_V_PER_LANE; i++)
        orow[i * 32 + lane] = xi[i];
}

extern "C" void kernel_launch(void* const* d_in, const int* in_sizes, int n_in,
                              void* d_out, int out_size)
{
    const float* x0 = (const float*)d_in[0];
    const float* W  = (const float*)d_in[1];
    const float* B  = (const float*)d_in[2];
    float* out      = (float*)d_out;

    const int batch = in_sizes[0] / CN_DIM;
    const int grid  = (batch + CN_ROWS_PER_BLOCK - 1) / CN_ROWS_PER_BLOCK;

    crossnet_fused_kernel<<<grid, CN_THREADS>>>(x0, W, B, out, batch);
}

// round 5
// speedup vs baseline: 1.1308x; 1.1308x over previous
#include <cuda_runtime.h>

// CrossNet collapsed form:
//   xi_l = c_l * x0 + d_l   (c scalar per row, d row-independent = running sum of B)
//   t_l  = x0 . w_l
//   c_{l+1} = c_l * (1 + t_l) + e_l,  e_l = d_l . w_l (row-independent const)
//   out  = c_3 * x0 + D,  D = B0+B1+B2
// Pre-kernel computes e1, e2, D once; main kernel does one pass over x0.

#define CN_DIM 1024
#define CN_ORDER 3
#define CN_ROWS_PER_BLOCK 8
#define CN_THREADS 256
#define CN_VEC (CN_DIM / 4)
#define CN_V_PER_LANE 8

__device__ float g_e[2];          // e1, e2
__device__ float g_D[CN_DIM];     // B0+B1+B2

// ---------------- pre-kernel: one block, computes e1, e2, D ----------------
__global__ void crossnet_prep_kernel(const float* __restrict__ W,
                                     const float* __restrict__ B)
{
    __shared__ float red1[CN_THREADS / 32];
    __shared__ float red2[CN_THREADS / 32];
    const int tid = threadIdx.x;

    float p1 = 0.0f, p2 = 0.0f;
    const float4* B0 = (const float4*)(B + 0 * CN_DIM);
    const float4* B1 = (const float4*)(B + 1 * CN_DIM);
    const float4* B2 = (const float4*)(B + 2 * CN_DIM);
    const float4* W1 = (const float4*)(W + 1 * CN_DIM);
    const float4* W2 = (const float4*)(W + 2 * CN_DIM);
    float4* Dv = (float4*)g_D;

    for (int i = tid; i < CN_VEC; i += CN_THREADS) {
        float4 b0 = B0[i], b1 = B1[i], b2 = B2[i];
        float4 w1 = W1[i], w2 = W2[i];
        // e1 = B0 . w1
        p1 = fmaf(b0.x, w1.x, p1); p1 = fmaf(b0.y, w1.y, p1);
        p1 = fmaf(b0.z, w1.z, p1); p1 = fmaf(b0.w, w1.w, p1);
        // e2 = (B0+B1) . w2
        float4 d2 = make_float4(b0.x + b1.x, b0.y + b1.y, b0.z + b1.z, b0.w + b1.w);
        p2 = fmaf(d2.x, w2.x, p2); p2 = fmaf(d2.y, w2.y, p2);
        p2 = fmaf(d2.z, w2.z, p2); p2 = fmaf(d2.w, w2.w, p2);
        // D = B0+B1+B2
        Dv[i] = make_float4(d2.x + b2.x, d2.y + b2.y, d2.z + b2.z, d2.w + b2.w);
    }

    #pragma unroll
    for (int off = 16; off > 0; off >>= 1) {
        p1 += __shfl_xor_sync(0xffffffffu, p1, off);
        p2 += __shfl_xor_sync(0xffffffffu, p2, off);
    }
    const int warp = tid >> 5, lane = tid & 31;
    if (lane == 0) { red1[warp] = p1; red2[warp] = p2; }
    __syncthreads();
    if (tid == 0) {
        float e1 = 0.0f, e2 = 0.0f;
        #pragma unroll
        for (int w = 0; w < CN_THREADS / 32; w++) { e1 += red1[w]; e2 += red2[w]; }
        g_e[0] = e1;
        g_e[1] = e2;
    }
}

// ---------------- main kernel: single pass over x0 ----------------
__global__ __launch_bounds__(CN_THREADS, 3)
void crossnet_main_kernel(const float* __restrict__ x0,
                          const float* __restrict__ W,
                          float* __restrict__ out,
                          int batch)
{
    __shared__ float sW[CN_ORDER * CN_DIM];
    __shared__ float sD[CN_DIM];
    __shared__ float sE[2];

    const int tid  = threadIdx.x;
    const int warp = tid >> 5;
    const int lane = tid & 31;
    const int row  = blockIdx.x * CN_ROWS_PER_BLOCK + warp;
    const bool active = (row < batch);

    // Fire the x0 row loads FIRST: 8 independent LDG.128 per lane overlap
    // the W/D staging below instead of waiting behind the barrier.
    const float4* __restrict__ xrow =
        (const float4*)(x0 + (size_t)(active ? row : 0) * CN_DIM);
    float4 x[CN_V_PER_LANE];
    #pragma unroll
    for (int i = 0; i < CN_V_PER_LANE; i++)
        x[i] = xrow[i * 32 + lane];

    // stage W (12 KB), D (4 KB), scalars into shared
    {
        const float4* gW = (const float4*)W;
        float4* shW = (float4*)sW;
        #pragma unroll
        for (int i = tid; i < CN_ORDER * CN_VEC; i += CN_THREADS)
            shW[i] = gW[i];
        const float4* gD = (const float4*)g_D;
        float4* shD = (float4*)sD;
        if (tid < CN_VEC) shD[tid] = gD[tid];
        if (tid < 2) sE[tid] = g_e[tid];
    }
    __syncthreads();
    if (!active) return;

    // three independent dots t_l = x0 . w_l, 2 accumulators each for ILP
    const float4* w0 = (const float4*)(sW + 0 * CN_DIM);
    const float4* w1 = (const float4*)(sW + 1 * CN_DIM);
    const float4* w2 = (const float4*)(sW + 2 * CN_DIM);

    float t0a = 0.f, t0b = 0.f, t1a = 0.f, t1b = 0.f, t2a = 0.f, t2b = 0.f;
    #pragma unroll
    for (int i = 0; i < CN_V_PER_LANE; i += 2) {
        float4 xa = x[i], xb = x[i + 1];
        float4 wa, wb;
        wa = w0[i * 32 + lane]; wb = w0[(i + 1) * 32 + lane];
        t0a = fmaf(xa.x, wa.x, t0a); t0a = fmaf(xa.y, wa.y, t0a);
        t0a = fmaf(xa.z, wa.z, t0a); t0a = fmaf(xa.w, wa.w, t0a);
        t0b = fmaf(xb.x, wb.x, t0b); t0b = fmaf(xb.y, wb.y, t0b);
        t0b = fmaf(xb.z, wb.z, t0b); t0b = fmaf(xb.w, wb.w, t0b);
        wa = w1[i * 32 + lane]; wb = w1[(i + 1) * 32 + lane];
        t1a = fmaf(xa.x, wa.x, t1a); t1a = fmaf(xa.y, wa.y, t1a);
        t1a = fmaf(xa.z, wa.z, t1a); t1a = fmaf(xa.w, wa.w, t1a);
        t1b = fmaf(xb.x, wb.x, t1b); t1b = fmaf(xb.y, wb.y, t1b);
        t1b = fmaf(xb.z, wb.z, t1b); t1b = fmaf(xb.w, wb.w, t1b);
        wa = w2[i * 32 + lane]; wb = w2[(i + 1) * 32 + lane];
        t2a = fmaf(xa.x, wa.x, t2a); t2a = fmaf(xa.y, wa.y, t2a);
        t2a = fmaf(xa.z, wa.z, t2a); t2a = fmaf(xa.w, wa.w, t2a);
        t2b = fmaf(xb.x, wb.x, t2b); t2b = fmaf(xb.y, wb.y, t2b);
        t2b = fmaf(xb.z, wb.z, t2b); t2b = fmaf(xb.w, wb.w, t2b);
    }
    float t0 = t0a + t0b, t1 = t1a + t1b, t2 = t2a + t2b;

    // warp reductions (independent, interleaved)
    #pragma unroll
    for (int off = 16; off > 0; off >>= 1) {
        t0 += __shfl_xor_sync(0xffffffffu, t0, off);
        t1 += __shfl_xor_sync(0xffffffffu, t1, off);
        t2 += __shfl_xor_sync(0xffffffffu, t2, off);
    }

    // scalar recurrence
    const float e1 = sE[0], e2 = sE[1];
    float c = 1.0f + t0;              // c1
    c = fmaf(c, t1, c) + e1;          // c2
    c = fmaf(c, t2, c) + e2;          // c3

    // out = c * x0 + D
    const float4* dv = (const float4*)sD;
    float4* __restrict__ orow = (float4*)(out + (size_t)row * CN_DIM);
    #pragma unroll
    for (int i = 0; i < CN_V_PER_LANE; i++) {
        float4 d = dv[i * 32 + lane];
        float4 o;
        o.x = fmaf(c, x[i].x, d.x);
        o.y = fmaf(c, x[i].y, d.y);
        o.z = fmaf(c, x[i].z, d.z);
        o.w = fmaf(c, x[i].w, d.w);
        orow[i * 32 + lane] = o;
    }
}

extern "C" void kernel_launch(void* const* d_in, const int* in_sizes, int n_in,
                              void* d_out, int out_size)
{
    const float* x0 = (const float*)d_in[0];
    const float* W  = (const float*)d_in[1];
    const float* B  = (const float*)d_in[2];
    float* out      = (float*)d_out;

    const int batch = in_sizes[0] / CN_DIM;
    const int grid  = (batch + CN_ROWS_PER_BLOCK - 1) / CN_ROWS_PER_BLOCK;

    crossnet_prep_kernel<<<1, CN_THREADS>>>(W, B);
    crossnet_main_kernel<<<grid, CN_THREADS>>>(x0, W, out, batch);
}